// round 2
// baseline (speedup 1.0000x reference)
#include <cuda_runtime.h>
#include <math.h>

// ---------------- problem constants ----------------
#define Bq   4
#define Tt   4096
#define HIDD 1024
#define NHh  16
#define QKd  64
#define VDd  64
#define KSs  4
#define REDd 128
#define Mrows (Bq*Tt)          // 16384
#define CHUNK 128
#define NCH   (Tt/CHUNK)       // 32

// ---------------- device scratch (no allocs allowed) ----------------
__device__ float g_Q   [Mrows*HIDD];        // 64 MB  (x@W_q + b_q, pre-RoPE)
__device__ float g_V   [Mrows*HIDD];        // 64 MB
__device__ float g_h   [Mrows*REDd];        //  8 MB  (silu hidden)
__device__ float g_ker [Mrows*NHh*KSs];     //  4 MB  (conv kernels)
__device__ float g_u   [Mrows*NHh];         //  1 MB
__device__ float g_vv  [Mrows*NHh];         //  1 MB
__device__ float g_attn[Mrows*HIDD];        // 64 MB  (scan output)
__device__ float g_A     [Bq*NHh*NCH];
__device__ float g_ctxend [Bq*NHh*NCH*VDd];
__device__ float g_ctxinit[Bq*NHh*NCH*VDd];

// dst selectors for the sgemm (avoid any host-side symbol addressing)
#define DST_Q    0
#define DST_V    1
#define DST_H    2
#define DST_EXT  3
#define SRC_EXT  0
#define SRC_ATTN 1

// ---------------- SGEMM: C = A[M,K] @ B[K,N] + bias, optional silu -----------
#define BM 128
#define BN 128
#define BK 8
#define TM 8
#define TN 8

__global__ __launch_bounds__(256) void sgemm_bias_kernel(
    const float* __restrict__ A_ext, int a_sel,
    const float* __restrict__ Bm,
    const float* __restrict__ bias,
    float* __restrict__ C_ext, int c_sel,
    int M, int N, int K, int act)
{
    const float* A = (a_sel == SRC_EXT) ? A_ext : (const float*)g_attn;
    float* C = (c_sel == DST_Q) ? g_Q
             : (c_sel == DST_V) ? g_V
             : (c_sel == DST_H) ? g_h
             : C_ext;

    __shared__ float As[2][BK][BM];
    __shared__ float Bs[2][BK][BN];

    const int tid = threadIdx.x;
    const int tx  = tid & 15;     // 16 col-threads
    const int ty  = tid >> 4;     // 16 row-threads

    const int rowBase = blockIdx.y * BM;
    const int colBase = blockIdx.x * BN;

    // global-load assignment
    const int a_row = tid >> 1;            // 0..127
    const int a_col = (tid & 1) << 2;      // 0 or 4
    const int b_row = tid >> 5;            // 0..7
    const int b_col = (tid & 31) << 2;     // 0..124

    const float* Ag = A  + (size_t)(rowBase + a_row) * K + a_col;
    const float* Bg = Bm + (size_t)b_row * N + colBase + b_col;

    float acc[TM][TN];
    #pragma unroll
    for (int i = 0; i < TM; i++)
        #pragma unroll
        for (int j = 0; j < TN; j++) acc[i][j] = 0.f;

    // prologue: stage 0
    float4 av = *(const float4*)(Ag);
    float4 bv = *(const float4*)(Bg);
    As[0][a_col+0][a_row] = av.x;
    As[0][a_col+1][a_row] = av.y;
    As[0][a_col+2][a_row] = av.z;
    As[0][a_col+3][a_row] = av.w;
    *(float4*)&Bs[0][b_row][b_col] = bv;
    __syncthreads();

    const int nk = K / BK;
    for (int kt = 0; kt < nk; kt++) {
        const int cur = kt & 1;
        if (kt + 1 < nk) {
            av = *(const float4*)(Ag + (kt+1)*BK);
            bv = *(const float4*)(Bg + (size_t)(kt+1)*BK*N);
        }
        #pragma unroll
        for (int kk = 0; kk < BK; kk++) {
            float a_frag[TM], b_frag[TN];
            #pragma unroll
            for (int i = 0; i < TM; i++) a_frag[i] = As[cur][kk][ty*TM + i];
            #pragma unroll
            for (int j = 0; j < TN; j++) b_frag[j] = Bs[cur][kk][tx*TN + j];
            #pragma unroll
            for (int i = 0; i < TM; i++)
                #pragma unroll
                for (int j = 0; j < TN; j++)
                    acc[i][j] += a_frag[i] * b_frag[j];
        }
        if (kt + 1 < nk) {
            const int nxt = cur ^ 1;
            As[nxt][a_col+0][a_row] = av.x;
            As[nxt][a_col+1][a_row] = av.y;
            As[nxt][a_col+2][a_row] = av.z;
            As[nxt][a_col+3][a_row] = av.w;
            *(float4*)&Bs[nxt][b_row][b_col] = bv;
        }
        __syncthreads();
    }

    // epilogue: bias + optional silu, float4 stores
    #pragma unroll
    for (int i = 0; i < TM; i++) {
        const int row = rowBase + ty*TM + i;
        #pragma unroll
        for (int j = 0; j < TN; j += 4) {
            const int col = colBase + tx*TN + j;
            float4 o;
            o.x = acc[i][j+0] + bias[col+0];
            o.y = acc[i][j+1] + bias[col+1];
            o.z = acc[i][j+2] + bias[col+2];
            o.w = acc[i][j+3] + bias[col+3];
            if (act) {
                o.x = o.x / (1.f + expf(-o.x));
                o.y = o.y / (1.f + expf(-o.y));
                o.z = o.z / (1.f + expf(-o.z));
                o.w = o.w / (1.f + expf(-o.w));
            }
            *(float4*)(C + (size_t)row * N + col) = o;
        }
    }
}

// ---------------- kernels = h @ kg_w2 + kg_b2  (K=128, N=64) -----------------
__global__ void kernels_kernel(const float* __restrict__ kg_w2,
                               const float* __restrict__ kg_b2)
{
    __shared__ float hs[REDd];
    const int row = blockIdx.x;          // 0..16383
    const int n   = threadIdx.x;         // 0..63
    hs[n]      = g_h[(size_t)row*REDd + n];
    hs[n + 64] = g_h[(size_t)row*REDd + n + 64];
    __syncthreads();
    float acc = kg_b2[n];
    #pragma unroll 8
    for (int k = 0; k < REDd; k++)
        acc += hs[k] * kg_w2[k*64 + n];
    g_ker[(size_t)row*64 + n] = acc;     // layout (b,t,h,ks) = row*64 + h*4 + ks
}

// ---------------- fused RoPE + gate:  u,v = sigmoid(rope(Q) @ gate_w + b) ----
__global__ void gate_kernel(const float* __restrict__ gate_w,
                            const float* __restrict__ gate_b)
{
    const int gw   = (blockIdx.x * blockDim.x + threadIdx.x) >> 5; // global warp
    const int lane = threadIdx.x & 31;
    const int h    = gw % NHh;
    const int bt   = gw / NHh;
    const int t    = bt % Tt;

    const float* q = g_Q + (size_t)bt * HIDD + h * QKd;
    const float q1 = q[lane];
    const float q2 = q[lane + 32];

    const float freq = powf(10000.0f, -(float)lane / 16.0f); // 10000^(-2i/32)
    float s, c;
    sincosf((float)t * freq, &s, &c);
    const float r1 = q1*c - q2*s;
    const float r2 = q1*s + q2*c;

    float du = r1*gate_w[lane*2]     + r2*gate_w[(lane+32)*2];
    float dv = r1*gate_w[lane*2 + 1] + r2*gate_w[(lane+32)*2 + 1];
    #pragma unroll
    for (int o = 16; o > 0; o >>= 1) {
        du += __shfl_down_sync(0xffffffffu, du, o);
        dv += __shfl_down_sync(0xffffffffu, dv, o);
    }
    if (lane == 0) {
        g_u [gw] = 1.f / (1.f + expf(-(du + gate_b[0])));
        g_vv[gw] = 1.f / (1.f + expf(-(dv + gate_b[1])));
    }
}

// ---------------- chunked scan (fused 4-tap Vmix) ----------------------------
// pass1: per chunk -> (prod u, local ctx end);  pass2: combine;  pass3: replay.
__global__ void scan_pass1()
{
    const int chunk = blockIdx.x;
    const int h     = blockIdx.y;
    const int b     = blockIdx.z;
    const int d     = threadIdx.x;       // 0..63
    const int bh    = b*NHh + h;
    const int t0    = chunk * CHUNK;

    const float* Vb   = g_V   + (size_t)(b*Tt)*HIDD + h*VDd + d;
    const float* kerB = g_ker + (size_t)(b*Tt)*NHh*KSs + h*KSs;
    const float* uB   = g_u   + (size_t)(b*Tt)*NHh + h;
    const float* vB   = g_vv  + (size_t)(b*Tt)*NHh + h;

    float v0 = (t0 >= 3) ? Vb[(size_t)(t0-3)*HIDD] : 0.f;
    float v1 = (t0 >= 2) ? Vb[(size_t)(t0-2)*HIDD] : 0.f;
    float v2 = (t0 >= 1) ? Vb[(size_t)(t0-1)*HIDD] : 0.f;

    float ctx = 0.f, Ap = 1.f;
    for (int tt = 0; tt < CHUNK; tt++) {
        const int t = t0 + tt;
        const float  v3 = Vb[(size_t)t*HIDD];
        const float4 kv = *(const float4*)(kerB + (size_t)t*NHh*KSs);
        const float  vm = kv.x*v0 + kv.y*v1 + kv.z*v2 + kv.w*v3;
        const float  uu = uB[(size_t)t*NHh];
        const float  vg = vB[(size_t)t*NHh];
        ctx = ctx*uu + vm*vg;
        Ap *= uu;
        v0 = v1; v1 = v2; v2 = v3;
    }
    g_ctxend[(size_t)(bh*NCH + chunk)*VDd + d] = ctx;
    if (d == 0) g_A[bh*NCH + chunk] = Ap;
}

__global__ void scan_pass2()
{
    const int bh = blockIdx.x;
    const int d  = threadIdx.x;
    float ctx = 0.f;
    for (int c = 0; c < NCH; c++) {
        g_ctxinit[(size_t)(bh*NCH + c)*VDd + d] = ctx;
        ctx = g_ctxend[(size_t)(bh*NCH + c)*VDd + d] + g_A[bh*NCH + c] * ctx;
    }
}

__global__ void scan_pass3()
{
    const int chunk = blockIdx.x;
    const int h     = blockIdx.y;
    const int b     = blockIdx.z;
    const int d     = threadIdx.x;
    const int bh    = b*NHh + h;
    const int t0    = chunk * CHUNK;

    const float* Vb   = g_V   + (size_t)(b*Tt)*HIDD + h*VDd + d;
    const float* kerB = g_ker + (size_t)(b*Tt)*NHh*KSs + h*KSs;
    const float* uB   = g_u   + (size_t)(b*Tt)*NHh + h;
    const float* vB   = g_vv  + (size_t)(b*Tt)*NHh + h;
    float*       Ob   = g_attn + (size_t)(b*Tt)*HIDD + h*VDd + d;

    float v0 = (t0 >= 3) ? Vb[(size_t)(t0-3)*HIDD] : 0.f;
    float v1 = (t0 >= 2) ? Vb[(size_t)(t0-2)*HIDD] : 0.f;
    float v2 = (t0 >= 1) ? Vb[(size_t)(t0-1)*HIDD] : 0.f;

    float ctx = g_ctxinit[(size_t)(bh*NCH + chunk)*VDd + d];
    for (int tt = 0; tt < CHUNK; tt++) {
        const int t = t0 + tt;
        const float  v3 = Vb[(size_t)t*HIDD];
        const float4 kv = *(const float4*)(kerB + (size_t)t*NHh*KSs);
        const float  vm = kv.x*v0 + kv.y*v1 + kv.z*v2 + kv.w*v3;
        const float  uu = uB[(size_t)t*NHh];
        const float  vg = vB[(size_t)t*NHh];
        ctx = ctx*uu + vm*vg;
        Ob[(size_t)t*HIDD] = ctx;
        v0 = v1; v1 = v2; v2 = v3;
    }
}

// ---------------- launch ----------------
extern "C" void kernel_launch(void* const* d_in, const int* in_sizes, int n_in,
                              void* d_out, int out_size)
{
    (void)in_sizes; (void)n_in; (void)out_size;
    const float* x      = (const float*)d_in[0];
    const float* W_q    = (const float*)d_in[1];
    const float* b_q    = (const float*)d_in[2];
    // d_in[3] = W_k, d_in[4] = b_k : DEAD in the reference — never used.
    const float* W_v    = (const float*)d_in[5];
    const float* b_v    = (const float*)d_in[6];
    const float* kg_w1  = (const float*)d_in[7];
    const float* kg_b1  = (const float*)d_in[8];
    const float* kg_w2  = (const float*)d_in[9];
    const float* kg_b2  = (const float*)d_in[10];
    const float* gate_w = (const float*)d_in[11];
    const float* gate_b = (const float*)d_in[12];
    const float* W_out  = (const float*)d_in[13];
    const float* b_out  = (const float*)d_in[14];
    float* out = (float*)d_out;

    const dim3 blk(256);
    // Q = x @ W_q + b_q
    sgemm_bias_kernel<<<dim3(HIDD/BN, Mrows/BM), blk>>>(x, SRC_EXT, W_q, b_q, nullptr, DST_Q, Mrows, HIDD, HIDD, 0);
    // V = x @ W_v + b_v
    sgemm_bias_kernel<<<dim3(HIDD/BN, Mrows/BM), blk>>>(x, SRC_EXT, W_v, b_v, nullptr, DST_V, Mrows, HIDD, HIDD, 0);
    // h = silu(x @ kg_w1 + kg_b1)
    sgemm_bias_kernel<<<dim3(REDd/BN, Mrows/BM), blk>>>(x, SRC_EXT, kg_w1, kg_b1, nullptr, DST_H, Mrows, REDd, HIDD, 1);
    // conv kernels
    kernels_kernel<<<Mrows, 64>>>(kg_w2, kg_b2);
    // fused RoPE + gate (u, v)
    gate_kernel<<<(Mrows*NHh)/4, 128>>>(gate_w, gate_b);
    // chunked linear scan with fused Vmix
    scan_pass1<<<dim3(NCH, NHh, Bq), VDd>>>();
    scan_pass2<<<Bq*NHh, VDd>>>();
    scan_pass3<<<dim3(NCH, NHh, Bq), VDd>>>();
    // out = attn @ W_out + b_out
    sgemm_bias_kernel<<<dim3(HIDD/BN, Mrows/BM), blk>>>(nullptr, SRC_ATTN, W_out, b_out, out, DST_EXT, Mrows, HIDD, HIDD, 0);
}

// round 7
// speedup vs baseline: 2.0303x; 2.0303x over previous
#include <cuda_runtime.h>
#include <cuda_bf16.h>
#include <stdint.h>
#include <string.h>
#include <math.h>

// ---------------- problem constants ----------------
#define Bq   4
#define Tt   4096
#define HIDD 1024
#define NHh  16
#define QKd  64
#define VDd  64
#define KSs  4
#define REDd 128
#define Mrows (Bq*Tt)          // 16384
#define CHUNK 128
#define NCH   (Tt/CHUNK)       // 32
#define KCH   32               // K chunks of 32 (K = 1024 for all GEMMs)

// ---------------- device scratch ----------------
__device__ __nv_bfloat16 g_xhi[(size_t)Mrows*HIDD];
__device__ __nv_bfloat16 g_xlo[(size_t)Mrows*HIDD];
__device__ __nv_bfloat16 g_ahi[(size_t)Mrows*HIDD];
__device__ __nv_bfloat16 g_alo[(size_t)Mrows*HIDD];
__device__ __nv_bfloat16 g_wqt_hi[HIDD*HIDD], g_wqt_lo[HIDD*HIDD];
__device__ __nv_bfloat16 g_wvt_hi[HIDD*HIDD], g_wvt_lo[HIDD*HIDD];
__device__ __nv_bfloat16 g_wot_hi[HIDD*HIDD], g_wot_lo[HIDD*HIDD];
__device__ __nv_bfloat16 g_kg1t_hi[REDd*HIDD], g_kg1t_lo[REDd*HIDD];
__device__ float g_Qf  [(size_t)Mrows*HIDD];
__device__ float g_V   [(size_t)Mrows*HIDD];
__device__ float g_h   [(size_t)Mrows*REDd];
__device__ float g_ker [(size_t)Mrows*NHh*KSs];
__device__ float g_u   [(size_t)Mrows*NHh];
__device__ float g_vv  [(size_t)Mrows*NHh];
__device__ float g_A      [Bq*NHh*NCH];
__device__ float g_ctxend [Bq*NHh*NCH*VDd];
__device__ float g_ctxinit[Bq*NHh*NCH*VDd];

// selectors
#define ASEL_X    0
#define ASEL_ATTN 1
#define BSEL_WQ   0
#define BSEL_WV   1
#define BSEL_KG1  2
#define BSEL_WO   3
#define CSEL_V    0
#define CSEL_H    1
#define CSEL_Q    2
#define CSEL_EXT  3
#define OSEL_WQ   0
#define OSEL_WV   1
#define OSEL_WO   2
#define OSEL_KG1  3

// ---------------- PTX helpers (sm_100-baseline safe: cp.async/ldmatrix/mma.sync) ----
__device__ __forceinline__ uint32_t smem_u32(const void* p) {
    uint32_t a;
    asm("{ .reg .u64 t; cvta.to.shared.u64 t, %1; cvt.u32.u64 %0, t; }" : "=r"(a) : "l"(p));
    return a;
}
#define CP16(dst, src) \
    asm volatile("cp.async.cg.shared.global [%0], [%1], 16;" :: "r"(dst), "l"(src))
#define CP_COMMIT() asm volatile("cp.async.commit_group;" ::: "memory")

__device__ __forceinline__ void ldsm4(uint32_t* r, uint32_t addr) {
    asm volatile("ldmatrix.sync.aligned.m8n8.x4.shared.b16 {%0,%1,%2,%3},[%4];"
        : "=r"(r[0]), "=r"(r[1]), "=r"(r[2]), "=r"(r[3]) : "r"(addr));
}
__device__ __forceinline__ void ldsm2(uint32_t* r, uint32_t addr) {
    asm volatile("ldmatrix.sync.aligned.m8n8.x2.shared.b16 {%0,%1},[%2];"
        : "=r"(r[0]), "=r"(r[1]) : "r"(addr));
}
__device__ __forceinline__ void mma16816(float* c, const uint32_t* a, const uint32_t* b) {
    asm volatile("mma.sync.aligned.m16n8k16.row.col.f32.bf16.bf16.f32 "
        "{%0,%1,%2,%3},{%4,%5,%6,%7},{%8,%9},{%0,%1,%2,%3};"
        : "+f"(c[0]), "+f"(c[1]), "+f"(c[2]), "+f"(c[3])
        : "r"(a[0]), "r"(a[1]), "r"(a[2]), "r"(a[3]), "r"(b[0]), "r"(b[1]));
}

// smem layout: 4 stages; per stage 4 matrices (Ahi,Alo,Bhi,Blo), each 128 rows x 80B (32 bf16 + pad)
#define ROW_B     80
#define MAT_BYTES (128*ROW_B)          // 10240
#define STG_BYTES (4*MAT_BYTES)        // 40960
#define SMEM_TOT  (4*STG_BYTES)        // 163840

__device__ __forceinline__ void load_stage(
    uint32_t sb, int st, int kc, int rowBase, int colBase,
    const __nv_bfloat16* Ahi, const __nv_bfloat16* Alo,
    const __nv_bfloat16* Bhi, const __nv_bfloat16* Blo, int tid)
{
    const uint32_t base = sb + st * STG_BYTES;
    const char* mats[4] = {
        (const char*)(Ahi + (size_t)rowBase * HIDD),
        (const char*)(Alo + (size_t)rowBase * HIDD),
        (const char*)(Bhi + (size_t)colBase * HIDD),
        (const char*)(Blo + (size_t)colBase * HIDD) };
    #pragma unroll
    for (int i = 0; i < 8; i++) {
        const int idx = i * 256 + tid;            // 2048 16B chunks
        const int m   = idx >> 9;
        const int row = (idx >> 2) & 127;
        const int ch  = idx & 3;
        CP16(base + m * MAT_BYTES + row * ROW_B + ch * 16,
             mats[m] + (size_t)row * (HIDD * 2) + kc * 64 + ch * 16);
    }
}

// ---------------- GEMM: C[M,N] = (Ahi+Alo) @ (Bhi+Blo)^T + bias -----------------
// B stored [N,K]. act: 0 = bias, 1 = bias + silu
__global__ __launch_bounds__(256, 1) void gemm_mma(
    int a_sel, int b_sel, int c_sel, float* __restrict__ C_ext,
    const float* __restrict__ bias, int ldC, int act)
{
    extern __shared__ char smem[];
    const uint32_t sb = smem_u32(smem);
    const int tid = threadIdx.x, wid = tid >> 5, lane = tid & 31;
    const int wm = wid >> 2, wn = wid & 3;        // 2 x 4 warp grid; warp tile 64 x 32
    const int rowBase = blockIdx.y * 128;
    const int colBase = blockIdx.x * 128;

    const __nv_bfloat16 *Ahi, *Alo, *Bhi, *Blo;
    if (a_sel == ASEL_X) { Ahi = g_xhi; Alo = g_xlo; } else { Ahi = g_ahi; Alo = g_alo; }
    if (b_sel == BSEL_WQ)       { Bhi = g_wqt_hi;  Blo = g_wqt_lo;  }
    else if (b_sel == BSEL_WV)  { Bhi = g_wvt_hi;  Blo = g_wvt_lo;  }
    else if (b_sel == BSEL_KG1) { Bhi = g_kg1t_hi; Blo = g_kg1t_lo; }
    else                        { Bhi = g_wot_hi;  Blo = g_wot_lo;  }
    float* C = (c_sel == CSEL_V) ? g_V : (c_sel == CSEL_H) ? g_h
             : (c_sel == CSEL_Q) ? g_Qf : C_ext;

    float acc[4][4][4];
    #pragma unroll
    for (int i = 0; i < 4; i++)
        #pragma unroll
        for (int j = 0; j < 4; j++)
            #pragma unroll
            for (int k = 0; k < 4; k++) acc[i][j][k] = 0.f;

    // prologue: 3 stages in flight
    load_stage(sb, 0, 0, rowBase, colBase, Ahi, Alo, Bhi, Blo, tid); CP_COMMIT();
    load_stage(sb, 1, 1, rowBase, colBase, Ahi, Alo, Bhi, Blo, tid); CP_COMMIT();
    load_stage(sb, 2, 2, rowBase, colBase, Ahi, Alo, Bhi, Blo, tid); CP_COMMIT();

    const int g  = lane >> 3;       // ldmatrix x4 group
    const int lr = lane & 7;

    for (int kc = 0; kc < KCH; kc++) {
        asm volatile("cp.async.wait_group 2;" ::: "memory");
        __syncthreads();
        // refill freed stage (consumed at iter kc-1)
        if (kc + 3 < KCH)
            load_stage(sb, (kc + 3) & 3, kc + 3, rowBase, colBase, Ahi, Alo, Bhi, Blo, tid);
        CP_COMMIT();   // uniform commit keeps wait_group arithmetic exact

        const uint32_t stb = sb + (kc & 3) * STG_BYTES;
        #pragma unroll
        for (int s = 0; s < 2; s++) {
            uint32_t ah[4][4], al[4][4], bh[4][2], bl[4][2];
            #pragma unroll
            for (int i = 0; i < 4; i++) {
                const uint32_t arow = (uint32_t)(wm * 64 + i * 16 + (g & 1) * 8 + lr);
                const uint32_t acol = (uint32_t)(s * 32 + (g >> 1) * 16);
                ldsm4(ah[i], stb +             arow * ROW_B + acol);
                ldsm4(al[i], stb + MAT_BYTES + arow * ROW_B + acol);
            }
            #pragma unroll
            for (int j = 0; j < 4; j++) {
                const uint32_t brow = (uint32_t)(wn * 32 + j * 8 + lr);
                const uint32_t bcol = (uint32_t)(s * 32 + (g & 1) * 16);
                ldsm2(bh[j], stb + 2 * MAT_BYTES + brow * ROW_B + bcol);
                ldsm2(bl[j], stb + 3 * MAT_BYTES + brow * ROW_B + bcol);
            }
            #pragma unroll
            for (int i = 0; i < 4; i++)
                #pragma unroll
                for (int j = 0; j < 4; j++) {
                    mma16816(acc[i][j], ah[i], bh[j]);
                    mma16816(acc[i][j], ah[i], bl[j]);
                    mma16816(acc[i][j], al[i], bh[j]);
                }
        }
    }

    // epilogue: bias (+ optional silu), direct register stores
    const int q = lane >> 2, r4 = lane & 3;
    #pragma unroll
    for (int i = 0; i < 4; i++) {
        const int row0 = rowBase + wm * 64 + i * 16 + q;
        #pragma unroll
        for (int j = 0; j < 4; j++) {
            const int col = colBase + wn * 32 + j * 8 + r4 * 2;
            const float b0 = bias[col], b1 = bias[col + 1];
            float v0 = acc[i][j][0] + b0, v1 = acc[i][j][1] + b1;
            float v2 = acc[i][j][2] + b0, v3 = acc[i][j][3] + b1;
            if (act == 1) {
                v0 = v0 / (1.f + expf(-v0));
                v1 = v1 / (1.f + expf(-v1));
                v2 = v2 / (1.f + expf(-v2));
                v3 = v3 / (1.f + expf(-v3));
            }
            *(float2*)(C + (size_t)row0 * ldC + col)       = make_float2(v0, v1);
            *(float2*)(C + (size_t)(row0 + 8) * ldC + col) = make_float2(v2, v3);
        }
    }
}

// ---------------- x -> bf16 hi/lo split ----------------
__global__ void convert_x_kernel(const float* __restrict__ x)
{
    const size_t i = (size_t)blockIdx.x * blockDim.x + threadIdx.x;  // float4 index
    const float4 v = ((const float4*)x)[i];
    unsigned short h[4], l[4];
    const float vv[4] = {v.x, v.y, v.z, v.w};
    #pragma unroll
    for (int j = 0; j < 4; j++) {
        __nv_bfloat16 hb = __float2bfloat16(vv[j]);
        __nv_bfloat16 lb = __float2bfloat16(vv[j] - __bfloat162float(hb));
        memcpy(&h[j], &hb, 2); memcpy(&l[j], &lb, 2);
    }
    uint2 H, L;
    H.x = (uint32_t)h[0] | ((uint32_t)h[1] << 16);
    H.y = (uint32_t)h[2] | ((uint32_t)h[3] << 16);
    L.x = (uint32_t)l[0] | ((uint32_t)l[1] << 16);
    L.y = (uint32_t)l[2] | ((uint32_t)l[3] << 16);
    ((uint2*)g_xhi)[i] = H;
    ((uint2*)g_xlo)[i] = L;
}

// ---------------- W[K,N] -> Wt_hi/lo [N,K] bf16 ----------------
__global__ void transpose_split_kernel(const float* __restrict__ W, int osel, int N)
{
    __shared__ float tile[32][33];
    const int n0 = blockIdx.x * 32, k0 = blockIdx.y * 32;
    const int tx = threadIdx.x, ty = threadIdx.y;   // 32 x 8
    #pragma unroll
    for (int j = 0; j < 32; j += 8)
        tile[ty + j][tx] = W[(size_t)(k0 + ty + j) * N + n0 + tx];
    __syncthreads();
    __nv_bfloat16 *hi, *lo;
    if (osel == OSEL_WQ)      { hi = g_wqt_hi;  lo = g_wqt_lo;  }
    else if (osel == OSEL_WV) { hi = g_wvt_hi;  lo = g_wvt_lo;  }
    else if (osel == OSEL_WO) { hi = g_wot_hi;  lo = g_wot_lo;  }
    else                      { hi = g_kg1t_hi; lo = g_kg1t_lo; }
    #pragma unroll
    for (int j = 0; j < 32; j += 8) {
        const int n = n0 + ty + j, k = k0 + tx;
        const float v = tile[tx][ty + j];
        __nv_bfloat16 hb = __float2bfloat16(v);
        hi[(size_t)n * HIDD + k] = hb;
        lo[(size_t)n * HIDD + k] = __float2bfloat16(v - __bfloat162float(hb));
    }
}

// ---------------- fused RoPE + gate (reads g_Qf, bias already added) ----------
__global__ void gate_kernel(const float* __restrict__ gate_w,
                            const float* __restrict__ gate_b)
{
    const int gw   = (blockIdx.x * blockDim.x + threadIdx.x) >> 5;
    const int lane = threadIdx.x & 31;
    const int h    = gw % NHh;
    const int bt   = gw / NHh;
    const int t    = bt % Tt;

    const float* qp = g_Qf + (size_t)bt * HIDD + h * QKd;
    const float q1 = qp[lane];
    const float q2 = qp[lane + 32];

    const float freq = powf(10000.0f, -(float)lane / 16.0f);
    float s, c;
    sincosf((float)t * freq, &s, &c);
    const float r1 = q1 * c - q2 * s;
    const float r2 = q1 * s + q2 * c;

    float du = r1 * gate_w[lane * 2]     + r2 * gate_w[(lane + 32) * 2];
    float dv = r1 * gate_w[lane * 2 + 1] + r2 * gate_w[(lane + 32) * 2 + 1];
    #pragma unroll
    for (int o = 16; o > 0; o >>= 1) {
        du += __shfl_down_sync(0xffffffffu, du, o);
        dv += __shfl_down_sync(0xffffffffu, dv, o);
    }
    if (lane == 0) {
        g_u [gw] = 1.f / (1.f + expf(-(du + gate_b[0])));
        g_vv[gw] = 1.f / (1.f + expf(-(dv + gate_b[1])));
    }
}

// ---------------- kernels = h @ kg_w2 + kg_b2 (smem-cached w2, 16 rows/block) --
__global__ __launch_bounds__(256) void kernels_kernel(const float* __restrict__ kg_w2,
                                                      const float* __restrict__ kg_b2)
{
    __shared__ float w2s[REDd][64];        // 32 KB
    __shared__ float hs[16][REDd + 4];     // 8.25 KB  -> total ~40.3 KB < 48 KB
    const int tid = threadIdx.x;
    const int row0 = blockIdx.x * 16;
    for (int i = tid; i < REDd * 64; i += 256) w2s[i >> 6][i & 63] = kg_w2[i];
    for (int i = tid; i < 16 * REDd; i += 256) {
        const int r = i >> 7, k = i & 127;
        hs[r][k] = g_h[(size_t)(row0 + r) * REDd + k];
    }
    __syncthreads();
    const int n = tid & 63;
    const int rg = tid >> 6;     // 4 groups x 4 rows
    const float bb = kg_b2[n];
    #pragma unroll
    for (int rr = 0; rr < 4; rr++) {
        const int r = rg * 4 + rr;
        float acc = bb;
        #pragma unroll 8
        for (int k = 0; k < REDd; k++) acc += hs[r][k] * w2s[k][n];
        g_ker[(size_t)(row0 + r) * 64 + n] = acc;
    }
}

// ---------------- chunked scan (fused 4-tap Vmix) ----------------
__global__ void scan_pass1()
{
    const int chunk = blockIdx.x, h = blockIdx.y, b = blockIdx.z;
    const int d = threadIdx.x;
    const int bh = b * NHh + h;
    const int t0 = chunk * CHUNK;
    const float* Vb   = g_V   + (size_t)(b * Tt) * HIDD + h * VDd + d;
    const float* kerB = g_ker + (size_t)(b * Tt) * NHh * KSs + h * KSs;
    const float* uB   = g_u   + (size_t)(b * Tt) * NHh + h;
    const float* vB   = g_vv  + (size_t)(b * Tt) * NHh + h;
    float v0 = (t0 >= 3) ? Vb[(size_t)(t0 - 3) * HIDD] : 0.f;
    float v1 = (t0 >= 2) ? Vb[(size_t)(t0 - 2) * HIDD] : 0.f;
    float v2 = (t0 >= 1) ? Vb[(size_t)(t0 - 1) * HIDD] : 0.f;
    float ctx = 0.f, Ap = 1.f;
    for (int tt = 0; tt < CHUNK; tt++) {
        const int t = t0 + tt;
        const float  v3 = Vb[(size_t)t * HIDD];
        const float4 kv = *(const float4*)(kerB + (size_t)t * NHh * KSs);
        const float  vm = kv.x * v0 + kv.y * v1 + kv.z * v2 + kv.w * v3;
        const float  uu = uB[(size_t)t * NHh];
        const float  vg = vB[(size_t)t * NHh];
        ctx = ctx * uu + vm * vg;
        Ap *= uu;
        v0 = v1; v1 = v2; v2 = v3;
    }
    g_ctxend[(size_t)(bh * NCH + chunk) * VDd + d] = ctx;
    if (d == 0) g_A[bh * NCH + chunk] = Ap;
}

__global__ void scan_pass2()
{
    const int bh = blockIdx.x, d = threadIdx.x;
    float ctx = 0.f;
    for (int c = 0; c < NCH; c++) {
        g_ctxinit[(size_t)(bh * NCH + c) * VDd + d] = ctx;
        ctx = g_ctxend[(size_t)(bh * NCH + c) * VDd + d] + g_A[bh * NCH + c] * ctx;
    }
}

__global__ void scan_pass3()
{
    const int chunk = blockIdx.x, h = blockIdx.y, b = blockIdx.z;
    const int d = threadIdx.x;
    const int bh = b * NHh + h;
    const int t0 = chunk * CHUNK;
    const float* Vb   = g_V   + (size_t)(b * Tt) * HIDD + h * VDd + d;
    const float* kerB = g_ker + (size_t)(b * Tt) * NHh * KSs + h * KSs;
    const float* uB   = g_u   + (size_t)(b * Tt) * NHh + h;
    const float* vB   = g_vv  + (size_t)(b * Tt) * NHh + h;
    const size_t obase = (size_t)(b * Tt) * HIDD + h * VDd + d;
    float v0 = (t0 >= 3) ? Vb[(size_t)(t0 - 3) * HIDD] : 0.f;
    float v1 = (t0 >= 2) ? Vb[(size_t)(t0 - 2) * HIDD] : 0.f;
    float v2 = (t0 >= 1) ? Vb[(size_t)(t0 - 1) * HIDD] : 0.f;
    float ctx = g_ctxinit[(size_t)(bh * NCH + chunk) * VDd + d];
    for (int tt = 0; tt < CHUNK; tt++) {
        const int t = t0 + tt;
        const float  v3 = Vb[(size_t)t * HIDD];
        const float4 kv = *(const float4*)(kerB + (size_t)t * NHh * KSs);
        const float  vm = kv.x * v0 + kv.y * v1 + kv.z * v2 + kv.w * v3;
        const float  uu = uB[(size_t)t * NHh];
        const float  vg = vB[(size_t)t * NHh];
        ctx = ctx * uu + vm * vg;
        __nv_bfloat16 hb = __float2bfloat16(ctx);
        g_ahi[obase + (size_t)t * HIDD] = hb;
        g_alo[obase + (size_t)t * HIDD] = __float2bfloat16(ctx - __bfloat162float(hb));
        v0 = v1; v1 = v2; v2 = v3;
    }
}

// ---------------- launch ----------------
extern "C" void kernel_launch(void* const* d_in, const int* in_sizes, int n_in,
                              void* d_out, int out_size)
{
    (void)in_sizes; (void)n_in; (void)out_size;
    const float* x      = (const float*)d_in[0];
    const float* W_q    = (const float*)d_in[1];
    const float* b_q    = (const float*)d_in[2];
    // d_in[3] = W_k, d_in[4] = b_k : dead in the reference
    const float* W_v    = (const float*)d_in[5];
    const float* b_v    = (const float*)d_in[6];
    const float* kg_w1  = (const float*)d_in[7];
    const float* kg_b1  = (const float*)d_in[8];
    const float* kg_w2  = (const float*)d_in[9];
    const float* kg_b2  = (const float*)d_in[10];
    const float* gate_w = (const float*)d_in[11];
    const float* gate_b = (const float*)d_in[12];
    const float* W_out  = (const float*)d_in[13];
    const float* b_out  = (const float*)d_in[14];
    float* out = (float*)d_out;

    cudaFuncSetAttribute(gemm_mma, cudaFuncAttributeMaxDynamicSharedMemorySize, SMEM_TOT);

    // input conversions
    convert_x_kernel<<<(Mrows * HIDD / 4) / 256, 256>>>(x);
    transpose_split_kernel<<<dim3(HIDD / 32, HIDD / 32), dim3(32, 8)>>>(W_q,   OSEL_WQ,  HIDD);
    transpose_split_kernel<<<dim3(HIDD / 32, HIDD / 32), dim3(32, 8)>>>(W_v,   OSEL_WV,  HIDD);
    transpose_split_kernel<<<dim3(HIDD / 32, HIDD / 32), dim3(32, 8)>>>(W_out, OSEL_WO,  HIDD);
    transpose_split_kernel<<<dim3(REDd / 32, HIDD / 32), dim3(32, 8)>>>(kg_w1, OSEL_KG1, REDd);

    // Q = x @ W_q + b_q (fp32 scratch for gate kernel)
    gemm_mma<<<dim3(HIDD / 128, Mrows / 128), 256, SMEM_TOT>>>(
        ASEL_X, BSEL_WQ, CSEL_Q, nullptr, b_q, HIDD, 0);
    // V = x @ W_v + b_v
    gemm_mma<<<dim3(HIDD / 128, Mrows / 128), 256, SMEM_TOT>>>(
        ASEL_X, BSEL_WV, CSEL_V, nullptr, b_v, HIDD, 0);
    // h = silu(x @ kg_w1 + kg_b1)
    gemm_mma<<<dim3(REDd / 128, Mrows / 128), 256, SMEM_TOT>>>(
        ASEL_X, BSEL_KG1, CSEL_H, nullptr, kg_b1, REDd, 1);
    // RoPE + gate
    gate_kernel<<<(Mrows * NHh) / 4, 128>>>(gate_w, gate_b);
    // conv kernels
    kernels_kernel<<<Mrows / 16, 256>>>(kg_w2, kg_b2);
    // chunked linear scan (pass3 writes bf16 hi/lo attn directly)
    scan_pass1<<<dim3(NCH, NHh, Bq), VDd>>>();
    scan_pass2<<<Bq * NHh, VDd>>>();
    scan_pass3<<<dim3(NCH, NHh, Bq), VDd>>>();
    // out = attn @ W_out + b_out
    gemm_mma<<<dim3(HIDD / 128, Mrows / 128), 256, SMEM_TOT>>>(
        ASEL_ATTN, BSEL_WO, CSEL_EXT, out, b_out, HIDD, 0);
}

// round 9
// speedup vs baseline: 2.6410x; 1.3007x over previous
#include <cuda_runtime.h>
#include <cuda_fp16.h>
#include <stdint.h>
#include <string.h>
#include <math.h>

// ---------------- problem constants ----------------
#define Bq   4
#define Tt   4096
#define HIDD 1024
#define NHh  16
#define QKd  64
#define VDd  64
#define KSs  4
#define REDd 128
#define Mrows (Bq*Tt)          // 16384
#define CHUNK 128
#define NCH   (Tt/CHUNK)       // 32
#define KCH   32               // K chunks of 32 (K = 1024 for all GEMMs)

// ---------------- device scratch ----------------
// A operands: single fp16 (error ~2^-12, recovered nowhere -> rel_err ~1e-4)
__device__ __half g_xh[(size_t)Mrows*HIDD];
__device__ __half g_ah[(size_t)Mrows*HIDD];
// B operands: fp16 hi+lo split (~22-bit effective mantissa, near exact)
__device__ __half g_wqt_hi[HIDD*HIDD], g_wqt_lo[HIDD*HIDD];
__device__ __half g_wvt_hi[HIDD*HIDD], g_wvt_lo[HIDD*HIDD];
__device__ __half g_wot_hi[HIDD*HIDD], g_wot_lo[HIDD*HIDD];
__device__ __half g_kg1t_hi[REDd*HIDD], g_kg1t_lo[REDd*HIDD];
__device__ float g_Qf  [(size_t)Mrows*HIDD];
__device__ float g_V   [(size_t)Mrows*HIDD];
__device__ float g_h   [(size_t)Mrows*REDd];
__device__ float g_ker [(size_t)Mrows*NHh*KSs];
__device__ float g_u   [(size_t)Mrows*NHh];
__device__ float g_vv  [(size_t)Mrows*NHh];
__device__ float g_A      [Bq*NHh*NCH];
__device__ float g_ctxend [Bq*NHh*NCH*VDd];
__device__ float g_ctxinit[Bq*NHh*NCH*VDd];

// selectors
#define ASEL_X    0
#define ASEL_ATTN 1
#define BSEL_WQ   0
#define BSEL_WV   1
#define BSEL_KG1  2
#define BSEL_WO   3
#define CSEL_V    0
#define CSEL_H    1
#define CSEL_Q    2
#define CSEL_EXT  3
#define OSEL_WQ   0
#define OSEL_WV   1
#define OSEL_WO   2
#define OSEL_KG1  3

// ---------------- PTX helpers (sm_100-baseline safe) ----------------
__device__ __forceinline__ uint32_t smem_u32(const void* p) {
    uint32_t a;
    asm("{ .reg .u64 t; cvta.to.shared.u64 t, %1; cvt.u32.u64 %0, t; }" : "=r"(a) : "l"(p));
    return a;
}
#define CP16(dst, src) \
    asm volatile("cp.async.cg.shared.global [%0], [%1], 16;" :: "r"(dst), "l"(src))
#define CP_COMMIT() asm volatile("cp.async.commit_group;" ::: "memory")

__device__ __forceinline__ void ldsm4(uint32_t* r, uint32_t addr) {
    asm volatile("ldmatrix.sync.aligned.m8n8.x4.shared.b16 {%0,%1,%2,%3},[%4];"
        : "=r"(r[0]), "=r"(r[1]), "=r"(r[2]), "=r"(r[3]) : "r"(addr));
}
__device__ __forceinline__ void ldsm2(uint32_t* r, uint32_t addr) {
    asm volatile("ldmatrix.sync.aligned.m8n8.x2.shared.b16 {%0,%1},[%2];"
        : "=r"(r[0]), "=r"(r[1]) : "r"(addr));
}
__device__ __forceinline__ void mma16816(float* c, const uint32_t* a, const uint32_t* b) {
    asm volatile("mma.sync.aligned.m16n8k16.row.col.f32.f16.f16.f32 "
        "{%0,%1,%2,%3},{%4,%5,%6,%7},{%8,%9},{%0,%1,%2,%3};"
        : "+f"(c[0]), "+f"(c[1]), "+f"(c[2]), "+f"(c[3])
        : "r"(a[0]), "r"(a[1]), "r"(a[2]), "r"(a[3]), "r"(b[0]), "r"(b[1]));
}

// smem: 4 stages; per stage 3 matrices (A, Bhi, Blo), each 128 rows x 80B (32 fp16 + pad)
#define ROW_B     80
#define MAT_BYTES (128*ROW_B)          // 10240
#define STG_BYTES (3*MAT_BYTES)        // 30720
#define SMEM_TOT  (4*STG_BYTES)        // 122880

__device__ __forceinline__ void load_stage(
    uint32_t sb, int st, int kc, int rowBase, int colBase,
    const __half* Aa, const __half* Bhi, const __half* Blo, int tid)
{
    const uint32_t base = sb + st * STG_BYTES;
    const char* mats[3] = {
        (const char*)(Aa  + (size_t)rowBase * HIDD),
        (const char*)(Bhi + (size_t)colBase * HIDD),
        (const char*)(Blo + (size_t)colBase * HIDD) };
    #pragma unroll
    for (int i = 0; i < 6; i++) {
        const int idx = i * 256 + tid;            // 1536 16B chunks
        const int m   = idx >> 9;
        const int row = (idx >> 2) & 127;
        const int ch  = idx & 3;
        CP16(base + m * MAT_BYTES + row * ROW_B + ch * 16,
             mats[m] + (size_t)row * (HIDD * 2) + kc * 64 + ch * 16);
    }
}

// ---------------- GEMM: C[M,N] = A @ (Bhi+Blo)^T + bias ------------------------
// B stored [N,K]. act: 0 = bias, 1 = bias + silu
__global__ __launch_bounds__(256, 1) void gemm_mma(
    int a_sel, int b_sel, int c_sel, float* __restrict__ C_ext,
    const float* __restrict__ bias, int ldC, int act)
{
    extern __shared__ char smem[];
    const uint32_t sb = smem_u32(smem);
    const int tid = threadIdx.x, wid = tid >> 5, lane = tid & 31;
    const int wm = wid >> 2, wn = wid & 3;        // 2 x 4 warp grid; warp tile 64 x 32
    const int rowBase = blockIdx.y * 128;
    const int colBase = blockIdx.x * 128;

    const __half *Aa, *Bhi, *Blo;
    Aa = (a_sel == ASEL_X) ? g_xh : g_ah;
    if (b_sel == BSEL_WQ)       { Bhi = g_wqt_hi;  Blo = g_wqt_lo;  }
    else if (b_sel == BSEL_WV)  { Bhi = g_wvt_hi;  Blo = g_wvt_lo;  }
    else if (b_sel == BSEL_KG1) { Bhi = g_kg1t_hi; Blo = g_kg1t_lo; }
    else                        { Bhi = g_wot_hi;  Blo = g_wot_lo;  }
    float* C = (c_sel == CSEL_V) ? g_V : (c_sel == CSEL_H) ? g_h
             : (c_sel == CSEL_Q) ? g_Qf : C_ext;

    float acc[4][4][4];
    #pragma unroll
    for (int i = 0; i < 4; i++)
        #pragma unroll
        for (int j = 0; j < 4; j++)
            #pragma unroll
            for (int k = 0; k < 4; k++) acc[i][j][k] = 0.f;

    // prologue: 3 stages in flight
    load_stage(sb, 0, 0, rowBase, colBase, Aa, Bhi, Blo, tid); CP_COMMIT();
    load_stage(sb, 1, 1, rowBase, colBase, Aa, Bhi, Blo, tid); CP_COMMIT();
    load_stage(sb, 2, 2, rowBase, colBase, Aa, Bhi, Blo, tid); CP_COMMIT();

    const int g  = lane >> 3;       // ldmatrix x4 group
    const int lr = lane & 7;

    for (int kc = 0; kc < KCH; kc++) {
        asm volatile("cp.async.wait_group 2;" ::: "memory");
        __syncthreads();
        if (kc + 3 < KCH)
            load_stage(sb, (kc + 3) & 3, kc + 3, rowBase, colBase, Aa, Bhi, Blo, tid);
        CP_COMMIT();   // uniform commit keeps wait_group arithmetic exact

        const uint32_t stb = sb + (kc & 3) * STG_BYTES;
        #pragma unroll
        for (int s = 0; s < 2; s++) {
            uint32_t ah[4][4], bh[4][2], bl[4][2];
            #pragma unroll
            for (int i = 0; i < 4; i++) {
                const uint32_t arow = (uint32_t)(wm * 64 + i * 16 + (g & 1) * 8 + lr);
                const uint32_t acol = (uint32_t)(s * 32 + (g >> 1) * 16);
                ldsm4(ah[i], stb + arow * ROW_B + acol);
            }
            #pragma unroll
            for (int j = 0; j < 4; j++) {
                const uint32_t brow = (uint32_t)(wn * 32 + j * 8 + lr);
                const uint32_t bcol = (uint32_t)(s * 32 + (g & 1) * 16);
                ldsm2(bh[j], stb +     MAT_BYTES + brow * ROW_B + bcol);
                ldsm2(bl[j], stb + 2 * MAT_BYTES + brow * ROW_B + bcol);
            }
            #pragma unroll
            for (int i = 0; i < 4; i++)
                #pragma unroll
                for (int j = 0; j < 4; j++) {
                    mma16816(acc[i][j], ah[i], bh[j]);
                    mma16816(acc[i][j], ah[i], bl[j]);
                }
        }
    }

    // epilogue: bias (+ optional silu), direct register stores
    const int q = lane >> 2, r4 = lane & 3;
    #pragma unroll
    for (int i = 0; i < 4; i++) {
        const int row0 = rowBase + wm * 64 + i * 16 + q;
        #pragma unroll
        for (int j = 0; j < 4; j++) {
            const int col = colBase + wn * 32 + j * 8 + r4 * 2;
            const float b0 = bias[col], b1 = bias[col + 1];
            float v0 = acc[i][j][0] + b0, v1 = acc[i][j][1] + b1;
            float v2 = acc[i][j][2] + b0, v3 = acc[i][j][3] + b1;
            if (act == 1) {
                v0 = v0 / (1.f + expf(-v0));
                v1 = v1 / (1.f + expf(-v1));
                v2 = v2 / (1.f + expf(-v2));
                v3 = v3 / (1.f + expf(-v3));
            }
            *(float2*)(C + (size_t)row0 * ldC + col)       = make_float2(v0, v1);
            *(float2*)(C + (size_t)(row0 + 8) * ldC + col) = make_float2(v2, v3);
        }
    }
}

// ---------------- x -> fp16 (single plane) ----------------
__global__ void convert_x_kernel(const float* __restrict__ x)
{
    const size_t i = (size_t)blockIdx.x * blockDim.x + threadIdx.x;  // float4 index
    const float4 v = ((const float4*)x)[i];
    __half2 lo = __floats2half2_rn(v.x, v.y);
    __half2 hi = __floats2half2_rn(v.z, v.w);
    uint2 H;
    memcpy(&H.x, &lo, 4);
    memcpy(&H.y, &hi, 4);
    ((uint2*)g_xh)[i] = H;
}

// ---------------- W[K,N] -> Wt_hi/lo [N,K] fp16 ----------------
__global__ void transpose_split_kernel(const float* __restrict__ W, int osel, int N)
{
    __shared__ float tile[32][33];
    const int n0 = blockIdx.x * 32, k0 = blockIdx.y * 32;
    const int tx = threadIdx.x, ty = threadIdx.y;   // 32 x 8
    #pragma unroll
    for (int j = 0; j < 32; j += 8)
        tile[ty + j][tx] = W[(size_t)(k0 + ty + j) * N + n0 + tx];
    __syncthreads();
    __half *hi, *lo;
    if (osel == OSEL_WQ)      { hi = g_wqt_hi;  lo = g_wqt_lo;  }
    else if (osel == OSEL_WV) { hi = g_wvt_hi;  lo = g_wvt_lo;  }
    else if (osel == OSEL_WO) { hi = g_wot_hi;  lo = g_wot_lo;  }
    else                      { hi = g_kg1t_hi; lo = g_kg1t_lo; }
    #pragma unroll
    for (int j = 0; j < 32; j += 8) {
        const int n = n0 + ty + j, k = k0 + tx;
        const float v = tile[tx][ty + j];
        __half hb = __float2half_rn(v);
        hi[(size_t)n * HIDD + k] = hb;
        lo[(size_t)n * HIDD + k] = __float2half_rn(v - __half2float(hb));
    }
}

// ---------------- fused RoPE + gate (reads g_Qf) ----------
__global__ void gate_kernel(const float* __restrict__ gate_w,
                            const float* __restrict__ gate_b)
{
    const int gw   = (blockIdx.x * blockDim.x + threadIdx.x) >> 5;
    const int lane = threadIdx.x & 31;
    const int h    = gw % NHh;
    const int bt   = gw / NHh;
    const int t    = bt % Tt;

    const float* qp = g_Qf + (size_t)bt * HIDD + h * QKd;
    const float q1 = qp[lane];
    const float q2 = qp[lane + 32];

    const float freq = powf(10000.0f, -(float)lane / 16.0f);
    float s, c;
    sincosf((float)t * freq, &s, &c);
    const float r1 = q1 * c - q2 * s;
    const float r2 = q1 * s + q2 * c;

    float du = r1 * gate_w[lane * 2]     + r2 * gate_w[(lane + 32) * 2];
    float dv = r1 * gate_w[lane * 2 + 1] + r2 * gate_w[(lane + 32) * 2 + 1];
    #pragma unroll
    for (int o = 16; o > 0; o >>= 1) {
        du += __shfl_down_sync(0xffffffffu, du, o);
        dv += __shfl_down_sync(0xffffffffu, dv, o);
    }
    if (lane == 0) {
        g_u [gw] = 1.f / (1.f + expf(-(du + gate_b[0])));
        g_vv[gw] = 1.f / (1.f + expf(-(dv + gate_b[1])));
    }
}

// ---------------- kernels = h @ kg_w2 + kg_b2 (smem-cached w2, 16 rows/block) --
__global__ __launch_bounds__(256) void kernels_kernel(const float* __restrict__ kg_w2,
                                                      const float* __restrict__ kg_b2)
{
    __shared__ float w2s[REDd][64];        // 32 KB
    __shared__ float hs[16][REDd + 4];     // 8.25 KB
    const int tid = threadIdx.x;
    const int row0 = blockIdx.x * 16;
    for (int i = tid; i < REDd * 64; i += 256) w2s[i >> 6][i & 63] = kg_w2[i];
    for (int i = tid; i < 16 * REDd; i += 256) {
        const int r = i >> 7, k = i & 127;
        hs[r][k] = g_h[(size_t)(row0 + r) * REDd + k];
    }
    __syncthreads();
    const int n = tid & 63;
    const int rg = tid >> 6;
    const float bb = kg_b2[n];
    #pragma unroll
    for (int rr = 0; rr < 4; rr++) {
        const int r = rg * 4 + rr;
        float acc = bb;
        #pragma unroll 8
        for (int k = 0; k < REDd; k++) acc += hs[r][k] * w2s[k][n];
        g_ker[(size_t)(row0 + r) * 64 + n] = acc;
    }
}

// ---------------- chunked scan (fused 4-tap Vmix) ----------------
__global__ void scan_pass1()
{
    const int chunk = blockIdx.x, h = blockIdx.y, b = blockIdx.z;
    const int d = threadIdx.x;
    const int bh = b * NHh + h;
    const int t0 = chunk * CHUNK;
    const float* Vb   = g_V   + (size_t)(b * Tt) * HIDD + h * VDd + d;
    const float* kerB = g_ker + (size_t)(b * Tt) * NHh * KSs + h * KSs;
    const float* uB   = g_u   + (size_t)(b * Tt) * NHh + h;
    const float* vB   = g_vv  + (size_t)(b * Tt) * NHh + h;
    float v0 = (t0 >= 3) ? Vb[(size_t)(t0 - 3) * HIDD] : 0.f;
    float v1 = (t0 >= 2) ? Vb[(size_t)(t0 - 2) * HIDD] : 0.f;
    float v2 = (t0 >= 1) ? Vb[(size_t)(t0 - 1) * HIDD] : 0.f;
    float ctx = 0.f, Ap = 1.f;
    for (int tt = 0; tt < CHUNK; tt++) {
        const int t = t0 + tt;
        const float  v3 = Vb[(size_t)t * HIDD];
        const float4 kv = *(const float4*)(kerB + (size_t)t * NHh * KSs);
        const float  vm = kv.x * v0 + kv.y * v1 + kv.z * v2 + kv.w * v3;
        const float  uu = uB[(size_t)t * NHh];
        const float  vg = vB[(size_t)t * NHh];
        ctx = ctx * uu + vm * vg;
        Ap *= uu;
        v0 = v1; v1 = v2; v2 = v3;
    }
    g_ctxend[(size_t)(bh * NCH + chunk) * VDd + d] = ctx;
    if (d == 0) g_A[bh * NCH + chunk] = Ap;
}

__global__ void scan_pass2()
{
    const int bh = blockIdx.x, d = threadIdx.x;
    float ctx = 0.f;
    for (int c = 0; c < NCH; c++) {
        g_ctxinit[(size_t)(bh * NCH + c) * VDd + d] = ctx;
        ctx = g_ctxend[(size_t)(bh * NCH + c) * VDd + d] + g_A[bh * NCH + c] * ctx;
    }
}

__global__ void scan_pass3()
{
    const int chunk = blockIdx.x, h = blockIdx.y, b = blockIdx.z;
    const int d = threadIdx.x;
    const int bh = b * NHh + h;
    const int t0 = chunk * CHUNK;
    const float* Vb   = g_V   + (size_t)(b * Tt) * HIDD + h * VDd + d;
    const float* kerB = g_ker + (size_t)(b * Tt) * NHh * KSs + h * KSs;
    const float* uB   = g_u   + (size_t)(b * Tt) * NHh + h;
    const float* vB   = g_vv  + (size_t)(b * Tt) * NHh + h;
    const size_t obase = (size_t)(b * Tt) * HIDD + h * VDd + d;
    float v0 = (t0 >= 3) ? Vb[(size_t)(t0 - 3) * HIDD] : 0.f;
    float v1 = (t0 >= 2) ? Vb[(size_t)(t0 - 2) * HIDD] : 0.f;
    float v2 = (t0 >= 1) ? Vb[(size_t)(t0 - 1) * HIDD] : 0.f;
    float ctx = g_ctxinit[(size_t)(bh * NCH + chunk) * VDd + d];
    for (int tt = 0; tt < CHUNK; tt++) {
        const int t = t0 + tt;
        const float  v3 = Vb[(size_t)t * HIDD];
        const float4 kv = *(const float4*)(kerB + (size_t)t * NHh * KSs);
        const float  vm = kv.x * v0 + kv.y * v1 + kv.z * v2 + kv.w * v3;
        const float  uu = uB[(size_t)t * NHh];
        const float  vg = vB[(size_t)t * NHh];
        ctx = ctx * uu + vm * vg;
        g_ah[obase + (size_t)t * HIDD] = __float2half_rn(ctx);
        v0 = v1; v1 = v2; v2 = v3;
    }
}

// ---------------- launch ----------------
extern "C" void kernel_launch(void* const* d_in, const int* in_sizes, int n_in,
                              void* d_out, int out_size)
{
    (void)in_sizes; (void)n_in; (void)out_size;
    const float* x      = (const float*)d_in[0];
    const float* W_q    = (const float*)d_in[1];
    const float* b_q    = (const float*)d_in[2];
    // d_in[3] = W_k, d_in[4] = b_k : dead in the reference
    const float* W_v    = (const float*)d_in[5];
    const float* b_v    = (const float*)d_in[6];
    const float* kg_w1  = (const float*)d_in[7];
    const float* kg_b1  = (const float*)d_in[8];
    const float* kg_w2  = (const float*)d_in[9];
    const float* kg_b2  = (const float*)d_in[10];
    const float* gate_w = (const float*)d_in[11];
    const float* gate_b = (const float*)d_in[12];
    const float* W_out  = (const float*)d_in[13];
    const float* b_out  = (const float*)d_in[14];
    float* out = (float*)d_out;

    cudaFuncSetAttribute(gemm_mma, cudaFuncAttributeMaxDynamicSharedMemorySize, SMEM_TOT);

    // input conversions
    convert_x_kernel<<<(Mrows * HIDD / 4) / 256, 256>>>(x);
    transpose_split_kernel<<<dim3(HIDD / 32, HIDD / 32), dim3(32, 8)>>>(W_q,   OSEL_WQ,  HIDD);
    transpose_split_kernel<<<dim3(HIDD / 32, HIDD / 32), dim3(32, 8)>>>(W_v,   OSEL_WV,  HIDD);
    transpose_split_kernel<<<dim3(HIDD / 32, HIDD / 32), dim3(32, 8)>>>(W_out, OSEL_WO,  HIDD);
    transpose_split_kernel<<<dim3(REDd / 32, HIDD / 32), dim3(32, 8)>>>(kg_w1, OSEL_KG1, REDd);

    // Q = x @ W_q + b_q (fp32 scratch for gate kernel)
    gemm_mma<<<dim3(HIDD / 128, Mrows / 128), 256, SMEM_TOT>>>(
        ASEL_X, BSEL_WQ, CSEL_Q, nullptr, b_q, HIDD, 0);
    // V = x @ W_v + b_v
    gemm_mma<<<dim3(HIDD / 128, Mrows / 128), 256, SMEM_TOT>>>(
        ASEL_X, BSEL_WV, CSEL_V, nullptr, b_v, HIDD, 0);
    // h = silu(x @ kg_w1 + kg_b1)
    gemm_mma<<<dim3(REDd / 128, Mrows / 128), 256, SMEM_TOT>>>(
        ASEL_X, BSEL_KG1, CSEL_H, nullptr, kg_b1, REDd, 1);
    // RoPE + gate
    gate_kernel<<<(Mrows * NHh) / 4, 128>>>(gate_w, gate_b);
    // conv kernels
    kernels_kernel<<<Mrows / 16, 256>>>(kg_w2, kg_b2);
    // chunked linear scan (pass3 writes fp16 attn directly)
    scan_pass1<<<dim3(NCH, NHh, Bq), VDd>>>();
    scan_pass2<<<Bq * NHh, VDd>>>();
    scan_pass3<<<dim3(NCH, NHh, Bq), VDd>>>();
    // out = attn @ W_out + b_out
    gemm_mma<<<dim3(HIDD / 128, Mrows / 128), 256, SMEM_TOT>>>(
        ASEL_ATTN, BSEL_WO, CSEL_EXT, out, b_out, HIDD, 0);
}

// round 10
// speedup vs baseline: 3.8692x; 1.4651x over previous
#include <cuda_runtime.h>
#include <cuda_fp16.h>
#include <stdint.h>
#include <string.h>
#include <math.h>

// ---------------- problem constants ----------------
#define Bq   4
#define Tt   4096
#define HIDD 1024
#define NHh  16
#define QKd  64
#define VDd  64
#define KSs  4
#define REDd 128
#define Mrows (Bq*Tt)          // 16384
#define CHUNK 128
#define NCH   (Tt/CHUNK)       // 32
#define KCH   32               // K chunks of 32 (K = 1024 for all GEMMs)

// ---------------- device scratch ----------------
// A and B operands: single fp16 (each ~2^-11 rel trunc; combined ~5e-4 final rel_err)
__device__ __half g_xh[(size_t)Mrows*HIDD];
__device__ __half g_ah[(size_t)Mrows*HIDD];
__device__ __half g_wqt[HIDD*HIDD];
__device__ __half g_wvt[HIDD*HIDD];
__device__ __half g_wot[HIDD*HIDD];
__device__ __half g_kg1t[REDd*HIDD];
__device__ float g_Qf  [(size_t)Mrows*HIDD];
__device__ float g_V   [(size_t)Mrows*HIDD];
__device__ float g_h   [(size_t)Mrows*REDd];
__device__ float g_ker [(size_t)Mrows*NHh*KSs];
__device__ float g_u   [(size_t)Mrows*NHh];
__device__ float g_vv  [(size_t)Mrows*NHh];
__device__ float g_A      [Bq*NHh*NCH];
__device__ float g_ctxend [Bq*NHh*NCH*VDd];
__device__ float g_ctxinit[Bq*NHh*NCH*VDd];

// selectors
#define ASEL_X    0
#define ASEL_ATTN 1
#define BSEL_WQ   0
#define BSEL_WV   1
#define BSEL_KG1  2
#define BSEL_WO   3
#define CSEL_V    0
#define CSEL_H    1
#define CSEL_Q    2
#define CSEL_EXT  3
#define OSEL_WQ   0
#define OSEL_WV   1
#define OSEL_WO   2
#define OSEL_KG1  3

// ---------------- PTX helpers (sm_100-baseline safe) ----------------
__device__ __forceinline__ uint32_t smem_u32(const void* p) {
    uint32_t a;
    asm("{ .reg .u64 t; cvta.to.shared.u64 t, %1; cvt.u32.u64 %0, t; }" : "=r"(a) : "l"(p));
    return a;
}
#define CP16(dst, src) \
    asm volatile("cp.async.cg.shared.global [%0], [%1], 16;" :: "r"(dst), "l"(src))
#define CP_COMMIT() asm volatile("cp.async.commit_group;" ::: "memory")

__device__ __forceinline__ void ldsm4(uint32_t* r, uint32_t addr) {
    asm volatile("ldmatrix.sync.aligned.m8n8.x4.shared.b16 {%0,%1,%2,%3},[%4];"
        : "=r"(r[0]), "=r"(r[1]), "=r"(r[2]), "=r"(r[3]) : "r"(addr));
}
__device__ __forceinline__ void ldsm2(uint32_t* r, uint32_t addr) {
    asm volatile("ldmatrix.sync.aligned.m8n8.x2.shared.b16 {%0,%1},[%2];"
        : "=r"(r[0]), "=r"(r[1]) : "r"(addr));
}
__device__ __forceinline__ void mma16816(float* c, const uint32_t* a, const uint32_t* b) {
    asm volatile("mma.sync.aligned.m16n8k16.row.col.f32.f16.f16.f32 "
        "{%0,%1,%2,%3},{%4,%5,%6,%7},{%8,%9},{%0,%1,%2,%3};"
        : "+f"(c[0]), "+f"(c[1]), "+f"(c[2]), "+f"(c[3])
        : "r"(a[0]), "r"(a[1]), "r"(a[2]), "r"(a[3]), "r"(b[0]), "r"(b[1]));
}

// smem: 4 stages; per stage 2 matrices (A, B), each 128 rows x 80B (32 fp16 + pad)
#define ROW_B     80
#define MAT_BYTES (128*ROW_B)          // 10240
#define STG_BYTES (2*MAT_BYTES)        // 20480
#define SMEM_TOT  (4*STG_BYTES)        // 81920

__device__ __forceinline__ void load_stage(
    uint32_t sb, int st, int kc, int rowBase, int colBase,
    const __half* Aa, const __half* Bb, int tid)
{
    const uint32_t base = sb + st * STG_BYTES;
    const char* mats[2] = {
        (const char*)(Aa + (size_t)rowBase * HIDD),
        (const char*)(Bb + (size_t)colBase * HIDD) };
    #pragma unroll
    for (int i = 0; i < 4; i++) {
        const int idx = i * 256 + tid;            // 1024 16B chunks
        const int m   = idx >> 9;
        const int row = (idx >> 2) & 127;
        const int ch  = idx & 3;
        CP16(base + m * MAT_BYTES + row * ROW_B + ch * 16,
             mats[m] + (size_t)row * (HIDD * 2) + kc * 64 + ch * 16);
    }
}

// ---------------- GEMM: C[M,N] = A @ B^T + bias --------------------------------
// B stored [N,K]. act: 0 = bias, 1 = bias + silu
__global__ __launch_bounds__(256, 1) void gemm_mma(
    int a_sel, int b_sel, int c_sel, float* __restrict__ C_ext,
    const float* __restrict__ bias, int ldC, int act)
{
    extern __shared__ char smem[];
    const uint32_t sb = smem_u32(smem);
    const int tid = threadIdx.x, wid = tid >> 5, lane = tid & 31;
    const int wm = wid >> 2, wn = wid & 3;        // 2 x 4 warp grid; warp tile 64 x 32
    const int rowBase = blockIdx.y * 128;
    const int colBase = blockIdx.x * 128;

    const __half *Aa, *Bb;
    Aa = (a_sel == ASEL_X) ? g_xh : g_ah;
    if (b_sel == BSEL_WQ)       Bb = g_wqt;
    else if (b_sel == BSEL_WV)  Bb = g_wvt;
    else if (b_sel == BSEL_KG1) Bb = g_kg1t;
    else                        Bb = g_wot;
    float* C = (c_sel == CSEL_V) ? g_V : (c_sel == CSEL_H) ? g_h
             : (c_sel == CSEL_Q) ? g_Qf : C_ext;

    float acc[4][4][4];
    #pragma unroll
    for (int i = 0; i < 4; i++)
        #pragma unroll
        for (int j = 0; j < 4; j++)
            #pragma unroll
            for (int k = 0; k < 4; k++) acc[i][j][k] = 0.f;

    // prologue: 3 stages in flight
    load_stage(sb, 0, 0, rowBase, colBase, Aa, Bb, tid); CP_COMMIT();
    load_stage(sb, 1, 1, rowBase, colBase, Aa, Bb, tid); CP_COMMIT();
    load_stage(sb, 2, 2, rowBase, colBase, Aa, Bb, tid); CP_COMMIT();

    const int g  = lane >> 3;       // ldmatrix x4 group
    const int lr = lane & 7;

    for (int kc = 0; kc < KCH; kc++) {
        asm volatile("cp.async.wait_group 2;" ::: "memory");
        __syncthreads();
        if (kc + 3 < KCH)
            load_stage(sb, (kc + 3) & 3, kc + 3, rowBase, colBase, Aa, Bb, tid);
        CP_COMMIT();   // uniform commit keeps wait_group arithmetic exact

        const uint32_t stb = sb + (kc & 3) * STG_BYTES;
        #pragma unroll
        for (int s = 0; s < 2; s++) {
            uint32_t ah[4][4], bh[4][2];
            #pragma unroll
            for (int i = 0; i < 4; i++) {
                const uint32_t arow = (uint32_t)(wm * 64 + i * 16 + (g & 1) * 8 + lr);
                const uint32_t acol = (uint32_t)(s * 32 + (g >> 1) * 16);
                ldsm4(ah[i], stb + arow * ROW_B + acol);
            }
            #pragma unroll
            for (int j = 0; j < 4; j++) {
                const uint32_t brow = (uint32_t)(wn * 32 + j * 8 + lr);
                const uint32_t bcol = (uint32_t)(s * 32 + (g & 1) * 16);
                ldsm2(bh[j], stb + MAT_BYTES + brow * ROW_B + bcol);
            }
            #pragma unroll
            for (int i = 0; i < 4; i++)
                #pragma unroll
                for (int j = 0; j < 4; j++)
                    mma16816(acc[i][j], ah[i], bh[j]);
        }
    }

    // epilogue: bias (+ optional silu), direct register stores
    const int q = lane >> 2, r4 = lane & 3;
    #pragma unroll
    for (int i = 0; i < 4; i++) {
        const int row0 = rowBase + wm * 64 + i * 16 + q;
        #pragma unroll
        for (int j = 0; j < 4; j++) {
            const int col = colBase + wn * 32 + j * 8 + r4 * 2;
            const float b0 = bias[col], b1 = bias[col + 1];
            float v0 = acc[i][j][0] + b0, v1 = acc[i][j][1] + b1;
            float v2 = acc[i][j][2] + b0, v3 = acc[i][j][3] + b1;
            if (act == 1) {
                v0 = v0 / (1.f + expf(-v0));
                v1 = v1 / (1.f + expf(-v1));
                v2 = v2 / (1.f + expf(-v2));
                v3 = v3 / (1.f + expf(-v3));
            }
            *(float2*)(C + (size_t)row0 * ldC + col)       = make_float2(v0, v1);
            *(float2*)(C + (size_t)(row0 + 8) * ldC + col) = make_float2(v2, v3);
        }
    }
}

// ---------------- x -> fp16 (single plane) ----------------
__global__ void convert_x_kernel(const float* __restrict__ x)
{
    const size_t i = (size_t)blockIdx.x * blockDim.x + threadIdx.x;  // float4 index
    const float4 v = ((const float4*)x)[i];
    __half2 lo = __floats2half2_rn(v.x, v.y);
    __half2 hi = __floats2half2_rn(v.z, v.w);
    uint2 H;
    memcpy(&H.x, &lo, 4);
    memcpy(&H.y, &hi, 4);
    ((uint2*)g_xh)[i] = H;
}

// ---------------- W[K,N] -> Wt [N,K] fp16 ----------------
__global__ void transpose_split_kernel(const float* __restrict__ W, int osel, int N)
{
    __shared__ float tile[32][33];
    const int n0 = blockIdx.x * 32, k0 = blockIdx.y * 32;
    const int tx = threadIdx.x, ty = threadIdx.y;   // 32 x 8
    #pragma unroll
    for (int j = 0; j < 32; j += 8)
        tile[ty + j][tx] = W[(size_t)(k0 + ty + j) * N + n0 + tx];
    __syncthreads();
    __half* dst;
    if (osel == OSEL_WQ)      dst = g_wqt;
    else if (osel == OSEL_WV) dst = g_wvt;
    else if (osel == OSEL_WO) dst = g_wot;
    else                      dst = g_kg1t;
    #pragma unroll
    for (int j = 0; j < 32; j += 8) {
        const int n = n0 + ty + j, k = k0 + tx;
        dst[(size_t)n * HIDD + k] = __float2half_rn(tile[tx][ty + j]);
    }
}

// ---------------- fused RoPE + gate (reads g_Qf) ----------
__global__ void gate_kernel(const float* __restrict__ gate_w,
                            const float* __restrict__ gate_b)
{
    const int gw   = (blockIdx.x * blockDim.x + threadIdx.x) >> 5;
    const int lane = threadIdx.x & 31;
    const int h    = gw % NHh;
    const int bt   = gw / NHh;
    const int t    = bt % Tt;

    const float* qp = g_Qf + (size_t)bt * HIDD + h * QKd;
    const float q1 = qp[lane];
    const float q2 = qp[lane + 32];

    const float freq = powf(10000.0f, -(float)lane / 16.0f);
    float s, c;
    sincosf((float)t * freq, &s, &c);
    const float r1 = q1 * c - q2 * s;
    const float r2 = q1 * s + q2 * c;

    float du = r1 * gate_w[lane * 2]     + r2 * gate_w[(lane + 32) * 2];
    float dv = r1 * gate_w[lane * 2 + 1] + r2 * gate_w[(lane + 32) * 2 + 1];
    #pragma unroll
    for (int o = 16; o > 0; o >>= 1) {
        du += __shfl_down_sync(0xffffffffu, du, o);
        dv += __shfl_down_sync(0xffffffffu, dv, o);
    }
    if (lane == 0) {
        g_u [gw] = 1.f / (1.f + expf(-(du + gate_b[0])));
        g_vv[gw] = 1.f / (1.f + expf(-(dv + gate_b[1])));
    }
}

// ---------------- kernels = h @ kg_w2 + kg_b2 (smem-cached w2, 16 rows/block) --
__global__ __launch_bounds__(256) void kernels_kernel(const float* __restrict__ kg_w2,
                                                      const float* __restrict__ kg_b2)
{
    __shared__ float w2s[REDd][64];        // 32 KB
    __shared__ float hs[16][REDd + 4];     // 8.25 KB
    const int tid = threadIdx.x;
    const int row0 = blockIdx.x * 16;
    for (int i = tid; i < REDd * 64; i += 256) w2s[i >> 6][i & 63] = kg_w2[i];
    for (int i = tid; i < 16 * REDd; i += 256) {
        const int r = i >> 7, k = i & 127;
        hs[r][k] = g_h[(size_t)(row0 + r) * REDd + k];
    }
    __syncthreads();
    const int n = tid & 63;
    const int rg = tid >> 6;
    const float bb = kg_b2[n];
    #pragma unroll
    for (int rr = 0; rr < 4; rr++) {
        const int r = rg * 4 + rr;
        float acc = bb;
        #pragma unroll 8
        for (int k = 0; k < REDd; k++) acc += hs[r][k] * w2s[k][n];
        g_ker[(size_t)(row0 + r) * 64 + n] = acc;
    }
}

// ---------------- chunked scan (fused 4-tap Vmix) ----------------
__global__ void scan_pass1()
{
    const int chunk = blockIdx.x, h = blockIdx.y, b = blockIdx.z;
    const int d = threadIdx.x;
    const int bh = b * NHh + h;
    const int t0 = chunk * CHUNK;
    const float* Vb   = g_V   + (size_t)(b * Tt) * HIDD + h * VDd + d;
    const float* kerB = g_ker + (size_t)(b * Tt) * NHh * KSs + h * KSs;
    const float* uB   = g_u   + (size_t)(b * Tt) * NHh + h;
    const float* vB   = g_vv  + (size_t)(b * Tt) * NHh + h;
    float v0 = (t0 >= 3) ? Vb[(size_t)(t0 - 3) * HIDD] : 0.f;
    float v1 = (t0 >= 2) ? Vb[(size_t)(t0 - 2) * HIDD] : 0.f;
    float v2 = (t0 >= 1) ? Vb[(size_t)(t0 - 1) * HIDD] : 0.f;
    float ctx = 0.f, Ap = 1.f;
    for (int tt = 0; tt < CHUNK; tt++) {
        const int t = t0 + tt;
        const float  v3 = Vb[(size_t)t * HIDD];
        const float4 kv = *(const float4*)(kerB + (size_t)t * NHh * KSs);
        const float  vm = kv.x * v0 + kv.y * v1 + kv.z * v2 + kv.w * v3;
        const float  uu = uB[(size_t)t * NHh];
        const float  vg = vB[(size_t)t * NHh];
        ctx = ctx * uu + vm * vg;
        Ap *= uu;
        v0 = v1; v1 = v2; v2 = v3;
    }
    g_ctxend[(size_t)(bh * NCH + chunk) * VDd + d] = ctx;
    if (d == 0) g_A[bh * NCH + chunk] = Ap;
}

__global__ void scan_pass2()
{
    const int bh = blockIdx.x, d = threadIdx.x;
    float ctx = 0.f;
    for (int c = 0; c < NCH; c++) {
        g_ctxinit[(size_t)(bh * NCH + c) * VDd + d] = ctx;
        ctx = g_ctxend[(size_t)(bh * NCH + c) * VDd + d] + g_A[bh * NCH + c] * ctx;
    }
}

__global__ void scan_pass3()
{
    const int chunk = blockIdx.x, h = blockIdx.y, b = blockIdx.z;
    const int d = threadIdx.x;
    const int bh = b * NHh + h;
    const int t0 = chunk * CHUNK;
    const float* Vb   = g_V   + (size_t)(b * Tt) * HIDD + h * VDd + d;
    const float* kerB = g_ker + (size_t)(b * Tt) * NHh * KSs + h * KSs;
    const float* uB   = g_u   + (size_t)(b * Tt) * NHh + h;
    const float* vB   = g_vv  + (size_t)(b * Tt) * NHh + h;
    const size_t obase = (size_t)(b * Tt) * HIDD + h * VDd + d;
    float v0 = (t0 >= 3) ? Vb[(size_t)(t0 - 3) * HIDD] : 0.f;
    float v1 = (t0 >= 2) ? Vb[(size_t)(t0 - 2) * HIDD] : 0.f;
    float v2 = (t0 >= 1) ? Vb[(size_t)(t0 - 1) * HIDD] : 0.f;
    float ctx = g_ctxinit[(size_t)(bh * NCH + chunk) * VDd + d];
    for (int tt = 0; tt < CHUNK; tt++) {
        const int t = t0 + tt;
        const float  v3 = Vb[(size_t)t * HIDD];
        const float4 kv = *(const float4*)(kerB + (size_t)t * NHh * KSs);
        const float  vm = kv.x * v0 + kv.y * v1 + kv.z * v2 + kv.w * v3;
        const float  uu = uB[(size_t)t * NHh];
        const float  vg = vB[(size_t)t * NHh];
        ctx = ctx * uu + vm * vg;
        g_ah[obase + (size_t)t * HIDD] = __float2half_rn(ctx);
        v0 = v1; v1 = v2; v2 = v3;
    }
}

// ---------------- launch ----------------
extern "C" void kernel_launch(void* const* d_in, const int* in_sizes, int n_in,
                              void* d_out, int out_size)
{
    (void)in_sizes; (void)n_in; (void)out_size;
    const float* x      = (const float*)d_in[0];
    const float* W_q    = (const float*)d_in[1];
    const float* b_q    = (const float*)d_in[2];
    // d_in[3] = W_k, d_in[4] = b_k : dead in the reference
    const float* W_v    = (const float*)d_in[5];
    const float* b_v    = (const float*)d_in[6];
    const float* kg_w1  = (const float*)d_in[7];
    const float* kg_b1  = (const float*)d_in[8];
    const float* kg_w2  = (const float*)d_in[9];
    const float* kg_b2  = (const float*)d_in[10];
    const float* gate_w = (const float*)d_in[11];
    const float* gate_b = (const float*)d_in[12];
    const float* W_out  = (const float*)d_in[13];
    const float* b_out  = (const float*)d_in[14];
    float* out = (float*)d_out;

    cudaFuncSetAttribute(gemm_mma, cudaFuncAttributeMaxDynamicSharedMemorySize, SMEM_TOT);

    // input conversions
    convert_x_kernel<<<(Mrows * HIDD / 4) / 256, 256>>>(x);
    transpose_split_kernel<<<dim3(HIDD / 32, HIDD / 32), dim3(32, 8)>>>(W_q,   OSEL_WQ,  HIDD);
    transpose_split_kernel<<<dim3(HIDD / 32, HIDD / 32), dim3(32, 8)>>>(W_v,   OSEL_WV,  HIDD);
    transpose_split_kernel<<<dim3(HIDD / 32, HIDD / 32), dim3(32, 8)>>>(W_out, OSEL_WO,  HIDD);
    transpose_split_kernel<<<dim3(REDd / 32, HIDD / 32), dim3(32, 8)>>>(kg_w1, OSEL_KG1, REDd);

    // Q = x @ W_q + b_q (fp32 scratch for gate kernel)
    gemm_mma<<<dim3(HIDD / 128, Mrows / 128), 256, SMEM_TOT>>>(
        ASEL_X, BSEL_WQ, CSEL_Q, nullptr, b_q, HIDD, 0);
    // V = x @ W_v + b_v
    gemm_mma<<<dim3(HIDD / 128, Mrows / 128), 256, SMEM_TOT>>>(
        ASEL_X, BSEL_WV, CSEL_V, nullptr, b_v, HIDD, 0);
    // h = silu(x @ kg_w1 + kg_b1)
    gemm_mma<<<dim3(REDd / 128, Mrows / 128), 256, SMEM_TOT>>>(
        ASEL_X, BSEL_KG1, CSEL_H, nullptr, kg_b1, REDd, 1);
    // RoPE + gate
    gate_kernel<<<(Mrows * NHh) / 4, 128>>>(gate_w, gate_b);
    // conv kernels
    kernels_kernel<<<Mrows / 16, 256>>>(kg_w2, kg_b2);
    // chunked linear scan (pass3 writes fp16 attn directly)
    scan_pass1<<<dim3(NCH, NHh, Bq), VDd>>>();
    scan_pass2<<<Bq * NHh, VDd>>>();
    scan_pass3<<<dim3(NCH, NHh, Bq), VDd>>>();
    // out = attn @ W_out + b_out
    gemm_mma<<<dim3(HIDD / 128, Mrows / 128), 256, SMEM_TOT>>>(
        ASEL_ATTN, BSEL_WO, CSEL_EXT, out, b_out, HIDD, 0);
}